// round 1
// baseline (speedup 1.0000x reference)
#include <cuda_runtime.h>
#include <cstdint>

#define TT 8192
#define HH 16
#define DD 128
#define KW 4
#define HD (HH * DD)        // 2048
#define C3 (3 * HD)         // 6144
#define NCB 8               // column blocks per head
#define CPB 16              // columns per block
#define NSUB 8              // k-subranges per column
#define KSUB 16             // k elements per subrange

typedef unsigned long long u64;

// ---------------- scratch (static device memory; no allocs allowed) --------
__device__ float g_q  [HH * TT * DD];   // [H][T][D]  64 MB
__device__ float g_k  [HH * TT * DD];   // [H][T][D]
__device__ float g_dec[HH * TT * DD];   // [H][T][D]
__device__ float g_v  [HH * TT * DD];   // [H][T][D]
__device__ float g_b  [HH * TT];        // [H][T]

// ---------------- packed f32x2 helpers (sm_103a) ---------------------------
__device__ __forceinline__ u64 fma2(u64 a, u64 b, u64 c) {
    u64 d; asm("fma.rn.f32x2 %0, %1, %2, %3;" : "=l"(d) : "l"(a), "l"(b), "l"(c)); return d;
}
__device__ __forceinline__ u64 mul2(u64 a, u64 b) {
    u64 d; asm("mul.rn.f32x2 %0, %1, %2;" : "=l"(d) : "l"(a), "l"(b)); return d;
}
__device__ __forceinline__ u64 add2(u64 a, u64 b) {
    u64 d; asm("add.rn.f32x2 %0, %1, %2;" : "=l"(d) : "l"(a), "l"(b)); return d;
}
__device__ __forceinline__ float hsum2(u64 a) {
    float x, y; asm("mov.b64 {%0, %1}, %2;" : "=f"(x), "=f"(y) : "l"(a)); return x + y;
}
__device__ __forceinline__ u64 pack2(float x) {
    u64 d; asm("mov.b64 %0, {%1, %1};" : "=l"(d) : "f"(x)); return d;
}

__device__ __forceinline__ float softplusf(float x) {
    return (x > 20.f) ? x : log1pf(expf(x));
}

// ============================================================================
// Phase 1: conv1d + SiLU, l2norm(q,k), gates  -> transposed [H][T][D] scratch
// ============================================================================
__global__ void prep_kernel(const float* __restrict__ xin,   // [T, 3HD]
                            const float* __restrict__ fg,    // [T, HD]
                            const float* __restrict__ beta,  // [T, H]
                            const float* __restrict__ cw,    // [3HD, 4]
                            const float* __restrict__ dtb,   // [H, D]
                            const float* __restrict__ alog)  // [H]
{
    const int t   = blockIdx.x;
    const int tid = threadIdx.x;                 // 256 threads

    __shared__ float sbuf[C3];
    __shared__ float snorm[32];

    // causal depthwise conv + SiLU
    for (int c = tid; c < C3; c += 256) {
        float4 w = ((const float4*)cw)[c];
        float acc = xin[(size_t)t * C3 + c] * w.w;
        if (t >= 1) acc += xin[(size_t)(t - 1) * C3 + c] * w.z;
        if (t >= 2) acc += xin[(size_t)(t - 2) * C3 + c] * w.y;
        if (t >= 3) acc += xin[(size_t)(t - 3) * C3 + c] * w.x;
        sbuf[c] = acc / (1.f + expf(-acc));      // silu
    }
    __syncthreads();

    // l2-norm factors: groups 0..15 = q heads (base g*128), 16..31 = k heads
    const int wid = tid >> 5, lane = tid & 31;
    for (int g = wid; g < 32; g += 8) {
        const int base = g * 128;
        float v0 = sbuf[base + lane];
        float v1 = sbuf[base + 32 + lane];
        float v2 = sbuf[base + 64 + lane];
        float v3 = sbuf[base + 96 + lane];
        float ss = v0 * v0 + v1 * v1 + v2 * v2 + v3 * v3;
        #pragma unroll
        for (int off = 16; off > 0; off >>= 1)
            ss += __shfl_xor_sync(0xffffffffu, ss, off);
        if (lane == 0) snorm[g] = rsqrtf(ss + 1e-6f);
    }
    __syncthreads();

    // write q, k, v into [H][T][D]
    const float qscale = 0.08838834764831845f;   // D^-0.5
    for (int c = tid; c < C3; c += 256) {
        float val = sbuf[c];
        if (c < HD) {
            int h = c >> 7, d = c & 127;
            g_q[((size_t)h * TT + t) * DD + d] = val * snorm[h] * qscale;
        } else if (c < 2 * HD) {
            int cc = c - HD; int h = cc >> 7, d = cc & 127;
            g_k[((size_t)h * TT + t) * DD + d] = val * snorm[16 + h];
        } else {
            int cc = c - 2 * HD; int h = cc >> 7, d = cc & 127;
            g_v[((size_t)h * TT + t) * DD + d] = val;
        }
    }

    // decay gate
    for (int cc = tid; cc < HD; cc += 256) {
        int h = cc >> 7, d = cc & 127;
        float g  = fg[(size_t)t * HD + cc] + dtb[h * DD + d];
        float sp = softplusf(g);
        g_dec[((size_t)h * TT + t) * DD + d] = expf(-expf(alog[h]) * sp);
    }
    if (tid < HH)
        g_b[tid * TT + t] = 1.f / (1.f + expf(-beta[(size_t)t * HH + tid]));
}

// ============================================================================
// Phase 2: per-(head, value-column) delta-rule scan.
// Grid (8, 16): blockIdx.x = column block, blockIdx.y = head. 128 threads.
// Thread = (col_local = tid>>3, sub = tid&7); state S[sub*16..+16, col] in regs
// as 8 packed f32x2. Column-reduce over 8 lanes with 3 SHFL.bfly.
// ============================================================================

#define LOADSET(K, Dc, Q, V, B, tt) do {                                     \
    const ulonglong2* _a = kp + (size_t)(tt) * 32;                           \
    ulonglong2 _x0 = _a[0], _x1 = _a[1], _x2 = _a[2], _x3 = _a[3];           \
    K[0]=_x0.x; K[1]=_x0.y; K[2]=_x1.x; K[3]=_x1.y;                          \
    K[4]=_x2.x; K[5]=_x2.y; K[6]=_x3.x; K[7]=_x3.y;                          \
    _a = dp + (size_t)(tt) * 32;                                             \
    _x0 = _a[0]; _x1 = _a[1]; _x2 = _a[2]; _x3 = _a[3];                      \
    Dc[0]=_x0.x; Dc[1]=_x0.y; Dc[2]=_x1.x; Dc[3]=_x1.y;                      \
    Dc[4]=_x2.x; Dc[5]=_x2.y; Dc[6]=_x3.x; Dc[7]=_x3.y;                      \
    _a = qp + (size_t)(tt) * 32;                                             \
    _x0 = _a[0]; _x1 = _a[1]; _x2 = _a[2]; _x3 = _a[3];                      \
    Q[0]=_x0.x; Q[1]=_x0.y; Q[2]=_x1.x; Q[3]=_x1.y;                          \
    Q[4]=_x2.x; Q[5]=_x2.y; Q[6]=_x3.x; Q[7]=_x3.y;                          \
    V = __ldg(vp + (size_t)(tt) * DD);                                       \
    B = __ldg(bp + (tt));                                                    \
} while (0)

#define STEP_COMPUTE(K, Dc, Q, V, B, tt) do {                                \
    u64 km0 = 0ull, km1 = 0ull;                                              \
    st[0] = mul2(st[0], Dc[0]);  st[1] = mul2(st[1], Dc[1]);                 \
    km0 = fma2(K[0], st[0], km0); km1 = fma2(K[1], st[1], km1);              \
    st[2] = mul2(st[2], Dc[2]);  st[3] = mul2(st[3], Dc[3]);                 \
    km0 = fma2(K[2], st[2], km0); km1 = fma2(K[3], st[3], km1);              \
    st[4] = mul2(st[4], Dc[4]);  st[5] = mul2(st[5], Dc[5]);                 \
    km0 = fma2(K[4], st[4], km0); km1 = fma2(K[5], st[5], km1);              \
    st[6] = mul2(st[6], Dc[6]);  st[7] = mul2(st[7], Dc[7]);                 \
    km0 = fma2(K[6], st[6], km0); km1 = fma2(K[7], st[7], km1);              \
    float km = hsum2(add2(km0, km1));                                        \
    km += __shfl_xor_sync(0xffffffffu, km, 1);                               \
    km += __shfl_xor_sync(0xffffffffu, km, 2);                               \
    km += __shfl_xor_sync(0xffffffffu, km, 4);                               \
    float delta = B * (V - km);                                              \
    u64 d2 = pack2(delta);                                                   \
    u64 o0 = 0ull, o1 = 0ull;                                                \
    st[0] = fma2(K[0], d2, st[0]); o0 = fma2(Q[0], st[0], o0);               \
    st[1] = fma2(K[1], d2, st[1]); o1 = fma2(Q[1], st[1], o1);               \
    st[2] = fma2(K[2], d2, st[2]); o0 = fma2(Q[2], st[2], o0);               \
    st[3] = fma2(K[3], d2, st[3]); o1 = fma2(Q[3], st[3], o1);               \
    st[4] = fma2(K[4], d2, st[4]); o0 = fma2(Q[4], st[4], o0);               \
    st[5] = fma2(K[5], d2, st[5]); o1 = fma2(Q[5], st[5], o1);               \
    st[6] = fma2(K[6], d2, st[6]); o0 = fma2(Q[6], st[6], o0);               \
    st[7] = fma2(K[7], d2, st[7]); o1 = fma2(Q[7], st[7], o1);               \
    float oo = hsum2(add2(o0, o1));                                          \
    oo += __shfl_xor_sync(0xffffffffu, oo, 1);                               \
    oo += __shfl_xor_sync(0xffffffffu, oo, 2);                               \
    oo += __shfl_xor_sync(0xffffffffu, oo, 4);                               \
    if (s == 0) op[(size_t)(tt) * HD] = oo;                                  \
} while (0)

__global__ void __launch_bounds__(128, 1)
kda_scan_kernel(float* __restrict__ out)
{
    const int h   = blockIdx.y;
    const int cb  = blockIdx.x;
    const int tid = threadIdx.x;
    const int cl  = tid >> 3;            // 0..15 column within block
    const int s   = tid & 7;             // k-subrange 0..7
    const int col = cb * CPB + cl;       // 0..127

    const size_t hbase = (size_t)h * TT * DD;
    const ulonglong2* kp = (const ulonglong2*)(g_k   + hbase + s * KSUB);
    const ulonglong2* dp = (const ulonglong2*)(g_dec + hbase + s * KSUB);
    const ulonglong2* qp = (const ulonglong2*)(g_q   + hbase + s * KSUB);
    const float* vp = g_v + hbase + col;
    const float* bp = g_b + (size_t)h * TT;
    float* op = out + (size_t)h * DD + col;      // + t*H*D per step

    u64 st[8];
    #pragma unroll
    for (int i = 0; i < 8; i++) st[i] = 0ull;

    u64 ka[8], da[8], qa[8];  float va, ba;
    u64 kb[8], db[8], qb[8];  float vb, bb;

    LOADSET(ka, da, qa, va, ba, 0);

    #pragma unroll 1
    for (int t = 0; t < TT; t += 2) {
        LOADSET(kb, db, qb, vb, bb, t + 1);
        STEP_COMPUTE(ka, da, qa, va, ba, t);
        if (t + 2 < TT) LOADSET(ka, da, qa, va, ba, t + 2);
        STEP_COMPUTE(kb, db, qb, vb, bb, t + 1);
    }
}

// ============================================================================
extern "C" void kernel_launch(void* const* d_in, const int* in_sizes, int n_in,
                              void* d_out, int out_size)
{
    const float* mixed = (const float*)d_in[0];   // [T, 3HD]
    const float* fg    = (const float*)d_in[1];   // [T, HD]
    const float* beta  = (const float*)d_in[2];   // [T, H]
    const float* cw    = (const float*)d_in[3];   // [3HD, 4]
    const float* dtb   = (const float*)d_in[4];   // [H, D]
    const float* alog  = (const float*)d_in[5];   // [H]
    float* out = (float*)d_out;                   // [T, H, D] f32

    prep_kernel<<<TT, 256>>>(mixed, fg, beta, cw, dtb, alog);
    kda_scan_kernel<<<dim3(NCB, HH), 128>>>(out);
}

// round 2
// speedup vs baseline: 3.1894x; 3.1894x over previous
#include <cuda_runtime.h>
#include <cstdint>

#define TT 8192
#define HH 16
#define DD 128
#define HD (HH * DD)        // 2048
#define C3 (3 * HD)         // 6144
#define NCB 8               // column blocks per head
#define CPB 16              // columns per block
#define GS 8                // steps per smem stage

typedef unsigned long long u64;

// ---------------- scratch (static device memory; no allocs allowed) --------
__device__ float g_q  [HH * TT * DD];   // [H][T][D]
__device__ float g_k  [HH * TT * DD];   // [H][T][D]
__device__ float g_dec[HH * TT * DD];   // [H][T][D]
__device__ float g_v  [HH * TT * DD];   // [H][T][D]
__device__ float g_b  [HH * TT];        // [H][T]

// ---------------- packed f32x2 helpers (sm_103a) ---------------------------
__device__ __forceinline__ u64 fma2(u64 a, u64 b, u64 c) {
    u64 d; asm("fma.rn.f32x2 %0, %1, %2, %3;" : "=l"(d) : "l"(a), "l"(b), "l"(c)); return d;
}
__device__ __forceinline__ u64 mul2(u64 a, u64 b) {
    u64 d; asm("mul.rn.f32x2 %0, %1, %2;" : "=l"(d) : "l"(a), "l"(b)); return d;
}
__device__ __forceinline__ u64 add2(u64 a, u64 b) {
    u64 d; asm("add.rn.f32x2 %0, %1, %2;" : "=l"(d) : "l"(a), "l"(b)); return d;
}
__device__ __forceinline__ float hsum2(u64 a) {
    float x, y; asm("mov.b64 {%0, %1}, %2;" : "=f"(x), "=f"(y) : "l"(a)); return x + y;
}
__device__ __forceinline__ u64 pack2(float x) {
    u64 d; asm("mov.b64 %0, {%1, %1};" : "=l"(d) : "f"(x)); return d;
}
__device__ __forceinline__ void cpa16(void* dst, const void* src) {
    unsigned d = (unsigned)__cvta_generic_to_shared(dst);
    asm volatile("cp.async.ca.shared.global [%0], [%1], 16;" :: "r"(d), "l"(src));
}

__device__ __forceinline__ float softplusf(float x) {
    return (x > 20.f) ? x : log1pf(expf(x));
}

// ============================================================================
// Phase 1: conv1d + SiLU, l2norm(q,k), gates  -> transposed [H][T][D] scratch
// (unchanged from R1 — correct, ~250us, not the bottleneck)
// ============================================================================
__global__ void prep_kernel(const float* __restrict__ xin,   // [T, 3HD]
                            const float* __restrict__ fg,    // [T, HD]
                            const float* __restrict__ beta,  // [T, H]
                            const float* __restrict__ cw,    // [3HD, 4]
                            const float* __restrict__ dtb,   // [H, D]
                            const float* __restrict__ alog)  // [H]
{
    const int t   = blockIdx.x;
    const int tid = threadIdx.x;                 // 256 threads

    __shared__ float sbuf[C3];
    __shared__ float snorm[32];

    for (int c = tid; c < C3; c += 256) {
        float4 w = ((const float4*)cw)[c];
        float acc = xin[(size_t)t * C3 + c] * w.w;
        if (t >= 1) acc += xin[(size_t)(t - 1) * C3 + c] * w.z;
        if (t >= 2) acc += xin[(size_t)(t - 2) * C3 + c] * w.y;
        if (t >= 3) acc += xin[(size_t)(t - 3) * C3 + c] * w.x;
        sbuf[c] = acc / (1.f + expf(-acc));      // silu
    }
    __syncthreads();

    const int wid = tid >> 5, lane = tid & 31;
    for (int g = wid; g < 32; g += 8) {
        const int base = g * 128;
        float v0 = sbuf[base + lane];
        float v1 = sbuf[base + 32 + lane];
        float v2 = sbuf[base + 64 + lane];
        float v3 = sbuf[base + 96 + lane];
        float ss = v0 * v0 + v1 * v1 + v2 * v2 + v3 * v3;
        #pragma unroll
        for (int off = 16; off > 0; off >>= 1)
            ss += __shfl_xor_sync(0xffffffffu, ss, off);
        if (lane == 0) snorm[g] = rsqrtf(ss + 1e-6f);
    }
    __syncthreads();

    const float qscale = 0.08838834764831845f;   // D^-0.5
    for (int c = tid; c < C3; c += 256) {
        float val = sbuf[c];
        if (c < HD) {
            int h = c >> 7, d = c & 127;
            g_q[((size_t)h * TT + t) * DD + d] = val * snorm[h] * qscale;
        } else if (c < 2 * HD) {
            int cc = c - HD; int h = cc >> 7, d = cc & 127;
            g_k[((size_t)h * TT + t) * DD + d] = val * snorm[16 + h];
        } else {
            int cc = c - 2 * HD; int h = cc >> 7, d = cc & 127;
            g_v[((size_t)h * TT + t) * DD + d] = val;
        }
    }

    for (int cc = tid; cc < HD; cc += 256) {
        int h = cc >> 7, d = cc & 127;
        float g  = fg[(size_t)t * HD + cc] + dtb[h * DD + d];
        float sp = softplusf(g);
        g_dec[((size_t)h * TT + t) * DD + d] = expf(-expf(alog[h]) * sp);
    }
    if (tid < HH)
        g_b[tid * TT + t] = 1.f / (1.f + expf(-beta[(size_t)t * HH + tid]));
}

// ============================================================================
// Phase 2: delta-rule scan with deep cp.async smem pipeline.
// Grid (8,16), 128 threads. cl=tid>>3 (column), s=tid&7 (k-subrange of 16).
// Smem: double buffer of GS=8 steps; k/dec/q rows stored chunk-swizzled so
// the 8 s-lanes hit 128 contiguous bytes per LDS.128 (conflict-free,
// broadcast across the 4 duplicated column groups).
// ============================================================================

// Load one step's operands from smem into register set S (A or B).
#define LOADR(S, buf, i) do {                                               \
    const ulonglong2* _p = &sk[buf][i][ss];                                 \
    ulonglong2 _c0 = _p[0], _c1 = _p[8], _c2 = _p[16], _c3 = _p[24];        \
    K##S[0]=_c0.x; K##S[1]=_c0.y; K##S[2]=_c1.x; K##S[3]=_c1.y;             \
    K##S[4]=_c2.x; K##S[5]=_c2.y; K##S[6]=_c3.x; K##S[7]=_c3.y;             \
    _p = &sd[buf][i][ss];                                                   \
    _c0 = _p[0]; _c1 = _p[8]; _c2 = _p[16]; _c3 = _p[24];                   \
    D##S[0]=_c0.x; D##S[1]=_c0.y; D##S[2]=_c1.x; D##S[3]=_c1.y;             \
    D##S[4]=_c2.x; D##S[5]=_c2.y; D##S[6]=_c3.x; D##S[7]=_c3.y;             \
    _p = &sq[buf][i][ss];                                                   \
    _c0 = _p[0]; _c1 = _p[8]; _c2 = _p[16]; _c3 = _p[24];                   \
    Q##S[0]=_c0.x; Q##S[1]=_c0.y; Q##S[2]=_c1.x; Q##S[3]=_c1.y;             \
    Q##S[4]=_c2.x; Q##S[5]=_c2.y; Q##S[6]=_c3.x; Q##S[7]=_c3.y;             \
    float _v = sv[buf][i][cl];                                              \
    b##S  = sb[buf][i];                                                     \
    bv##S = b##S * _v;                                                      \
} while (0)

#define STEP(S, tt) do {                                                    \
    u64 km0 = 0ull, km1 = 0ull;                                             \
    st[0] = mul2(st[0], D##S[0]);  st[1] = mul2(st[1], D##S[1]);            \
    km0 = fma2(K##S[0], st[0], km0); km1 = fma2(K##S[1], st[1], km1);       \
    st[2] = mul2(st[2], D##S[2]);  st[3] = mul2(st[3], D##S[3]);            \
    km0 = fma2(K##S[2], st[2], km0); km1 = fma2(K##S[3], st[3], km1);       \
    st[4] = mul2(st[4], D##S[4]);  st[5] = mul2(st[5], D##S[5]);            \
    km0 = fma2(K##S[4], st[4], km0); km1 = fma2(K##S[5], st[5], km1);       \
    st[6] = mul2(st[6], D##S[6]);  st[7] = mul2(st[7], D##S[7]);            \
    km0 = fma2(K##S[6], st[6], km0); km1 = fma2(K##S[7], st[7], km1);       \
    float km = hsum2(add2(km0, km1));                                       \
    km += __shfl_xor_sync(0xffffffffu, km, 1);                              \
    km += __shfl_xor_sync(0xffffffffu, km, 2);                              \
    km += __shfl_xor_sync(0xffffffffu, km, 4);                              \
    float delta = fmaf(-b##S, km, bv##S);                                   \
    u64 d2 = pack2(delta);                                                  \
    u64 o0 = 0ull, o1 = 0ull;                                               \
    st[0] = fma2(K##S[0], d2, st[0]); o0 = fma2(Q##S[0], st[0], o0);        \
    st[1] = fma2(K##S[1], d2, st[1]); o1 = fma2(Q##S[1], st[1], o1);        \
    st[2] = fma2(K##S[2], d2, st[2]); o0 = fma2(Q##S[2], st[2], o0);        \
    st[3] = fma2(K##S[3], d2, st[3]); o1 = fma2(Q##S[3], st[3], o1);        \
    st[4] = fma2(K##S[4], d2, st[4]); o0 = fma2(Q##S[4], st[4], o0);        \
    st[5] = fma2(K##S[5], d2, st[5]); o1 = fma2(Q##S[5], st[5], o1);        \
    st[6] = fma2(K##S[6], d2, st[6]); o0 = fma2(Q##S[6], st[6], o0);        \
    st[7] = fma2(K##S[7], d2, st[7]); o1 = fma2(Q##S[7], st[7], o1);        \
    float oo = hsum2(add2(o0, o1));                                         \
    oo += __shfl_xor_sync(0xffffffffu, oo, 1);                              \
    oo += __shfl_xor_sync(0xffffffffu, oo, 2);                              \
    oo += __shfl_xor_sync(0xffffffffu, oo, 4);                              \
    if (s == 0) op[(size_t)(tt) * HD] = oo;                                 \
} while (0)

// Prefetch one GS-step stage into buffer `buf` starting at time t0.
#define PREFETCH(buf, t0) do {                                              \
    _Pragma("unroll")                                                       \
    for (int _j = 0; _j < 2; _j++) {                                        \
        int _c = tid + _j * 128;                                            \
        int _st = _c >> 5, _cc = _c & 31;                                   \
        int _pos = ((_cc & 3) << 3) | (_cc >> 2);                           \
        size_t _go = (size_t)((t0) + _st) * DD + _cc * 4;                   \
        cpa16(&sk[buf][_st][_pos], kg + _go);                               \
        cpa16(&sd[buf][_st][_pos], dg + _go);                               \
        cpa16(&sq[buf][_st][_pos], qg + _go);                               \
    }                                                                       \
    if (tid < 32) {                                                         \
        int _st = tid >> 2, _part = tid & 3;                                \
        cpa16(&sv[buf][_st][_part * 4],                                     \
              vg + (size_t)((t0) + _st) * DD + _part * 4);                  \
    } else if (tid < 34) {                                                  \
        int _j = tid - 32;                                                  \
        cpa16(&sb[buf][_j * 4], bg + (t0) + _j * 4);                        \
    }                                                                       \
} while (0)

__global__ void __launch_bounds__(128, 1)
kda_scan_kernel(float* __restrict__ out)
{
    __shared__ __align__(16) ulonglong2 sk[2][GS][32];
    __shared__ __align__(16) ulonglong2 sd[2][GS][32];
    __shared__ __align__(16) ulonglong2 sq[2][GS][32];
    __shared__ __align__(16) float      sv[2][GS][16];
    __shared__ __align__(16) float      sb[2][GS];

    const int h   = blockIdx.y;
    const int cb  = blockIdx.x;
    const int tid = threadIdx.x;
    const int cl  = tid >> 3;            // 0..15 column within block
    const int s   = tid & 7;             // k-subrange 0..7
    const int ss  = s;                   // smem chunk lane index
    const int col = cb * CPB + cl;

    const size_t hbase = (size_t)h * TT * DD;
    const float* kg = g_k   + hbase;
    const float* dg = g_dec + hbase;
    const float* qg = g_q   + hbase;
    const float* vg = g_v   + hbase + cb * CPB;
    const float* bg = g_b   + (size_t)h * TT;
    float* op = out + (size_t)h * DD + col;     // + t*H*D per step

    u64 st[8];
    #pragma unroll
    for (int i = 0; i < 8; i++) st[i] = 0ull;

    u64 KA[8], DA[8], QA[8], KB[8], DB[8], QB[8];
    float bA, bvA, bB, bvB;

    PREFETCH(0, 0);
    asm volatile("cp.async.commit_group;" ::: "memory");
    PREFETCH(1, GS);
    asm volatile("cp.async.commit_group;" ::: "memory");

    #pragma unroll 1
    for (int t0 = 0; t0 < TT; t0 += GS) {
        const int buf = (t0 >> 3) & 1;
        asm volatile("cp.async.wait_group 1;" ::: "memory");
        __syncthreads();

        LOADR(A, buf, 0);
        #pragma unroll
        for (int i = 0; i < GS; i += 2) {
            LOADR(B, buf, i + 1);
            STEP(A, t0 + i);
            if (i + 2 < GS) LOADR(A, buf, i + 2);
            STEP(B, t0 + i + 1);
        }

        __syncthreads();
        if (t0 + 2 * GS < TT) {
            PREFETCH(buf, t0 + 2 * GS);
        }
        asm volatile("cp.async.commit_group;" ::: "memory");
    }
}

// ============================================================================
extern "C" void kernel_launch(void* const* d_in, const int* in_sizes, int n_in,
                              void* d_out, int out_size)
{
    const float* mixed = (const float*)d_in[0];   // [T, 3HD]
    const float* fg    = (const float*)d_in[1];   // [T, HD]
    const float* beta  = (const float*)d_in[2];   // [T, H]
    const float* cw    = (const float*)d_in[3];   // [3HD, 4]
    const float* dtb   = (const float*)d_in[4];   // [H, D]
    const float* alog  = (const float*)d_in[5];   // [H]
    float* out = (float*)d_out;                   // [T, H, D] f32

    prep_kernel<<<TT, 256>>>(mixed, fg, beta, cw, dtb, alog);
    kda_scan_kernel<<<dim3(NCB, HH), 128>>>(out);
}

// round 3
// speedup vs baseline: 3.5910x; 1.1259x over previous
#include <cuda_runtime.h>
#include <cstdint>

#define TT 8192
#define HH 16
#define DD 128
#define HD (HH * DD)        // 2048
#define C3 (3 * HD)         // 6144
#define NCB 8               // column blocks per head
#define CPB 16              // columns per block
#define GS 8                // steps per smem stage

typedef unsigned long long u64;

// ---------------- scratch (static device memory; no allocs allowed) --------
__device__ float g_q  [HH * TT * DD];   // [H][T][D]
__device__ float g_k  [HH * TT * DD];   // [H][T][D]
__device__ float g_dec[HH * TT * DD];   // [H][T][D]
__device__ float g_v  [HH * TT * DD];   // [H][T][D]
__device__ float g_b  [HH * TT];        // [H][T]

// ---------------- packed f32x2 helpers (sm_103a) ---------------------------
__device__ __forceinline__ u64 fma2(u64 a, u64 b, u64 c) {
    u64 d; asm("fma.rn.f32x2 %0, %1, %2, %3;" : "=l"(d) : "l"(a), "l"(b), "l"(c)); return d;
}
__device__ __forceinline__ u64 mul2(u64 a, u64 b) {
    u64 d; asm("mul.rn.f32x2 %0, %1, %2;" : "=l"(d) : "l"(a), "l"(b)); return d;
}
__device__ __forceinline__ u64 add2(u64 a, u64 b) {
    u64 d; asm("add.rn.f32x2 %0, %1, %2;" : "=l"(d) : "l"(a), "l"(b)); return d;
}
__device__ __forceinline__ float hsum2(u64 a) {
    float x, y; asm("mov.b64 {%0, %1}, %2;" : "=f"(x), "=f"(y) : "l"(a)); return x + y;
}
__device__ __forceinline__ u64 pack2(float x) {
    u64 d; asm("mov.b64 %0, {%1, %1};" : "=l"(d) : "f"(x)); return d;
}
__device__ __forceinline__ void cpa16(void* dst, const void* src) {
    unsigned d = (unsigned)__cvta_generic_to_shared(dst);
    asm volatile("cp.async.ca.shared.global [%0], [%1], 16;" :: "r"(d), "l"(src));
}

__device__ __forceinline__ float softplusf(float x) {
    return (x > 20.f) ? x : log1pf(expf(x));
}

// ============================================================================
// Phase 1: conv1d + SiLU, l2norm(q,k), gates  -> transposed [H][T][D] scratch
// float4-ized loads/stores.
// ============================================================================
__global__ void prep_kernel(const float* __restrict__ xin,   // [T, 3HD]
                            const float* __restrict__ fg,    // [T, HD]
                            const float* __restrict__ beta,  // [T, H]
                            const float* __restrict__ cw,    // [3HD, 4]
                            const float* __restrict__ dtb,   // [H, D]
                            const float* __restrict__ alog)  // [H]
{
    const int t   = blockIdx.x;
    const int tid = threadIdx.x;                 // 256 threads

    __shared__ float sbuf[C3];
    __shared__ float snorm[32];
    __shared__ float snegA[HH];

    if (tid < HH) snegA[tid] = -expf(alog[tid]);

    const float4* x4  = (const float4*)xin;      // [T, 1536]
    const float4* w4  = (const float4*)cw;       // [6144] rows of 4
    float4* sbuf4 = (float4*)sbuf;

    // causal depthwise conv + SiLU (vectorized over 4 channels)
    #pragma unroll
    for (int it = 0; it < 6; it++) {
        int c4 = tid + it * 256;                 // 0..1535
        float4 w0 = w4[c4 * 4 + 0];
        float4 w1 = w4[c4 * 4 + 1];
        float4 w2 = w4[c4 * 4 + 2];
        float4 w3 = w4[c4 * 4 + 3];
        float4 a0 = x4[(size_t)t * 1536 + c4];
        float4 acc;
        acc.x = a0.x * w0.w; acc.y = a0.y * w1.w;
        acc.z = a0.z * w2.w; acc.w = a0.w * w3.w;
        if (t >= 1) {
            float4 a = x4[(size_t)(t - 1) * 1536 + c4];
            acc.x += a.x * w0.z; acc.y += a.y * w1.z;
            acc.z += a.z * w2.z; acc.w += a.w * w3.z;
        }
        if (t >= 2) {
            float4 a = x4[(size_t)(t - 2) * 1536 + c4];
            acc.x += a.x * w0.y; acc.y += a.y * w1.y;
            acc.z += a.z * w2.y; acc.w += a.w * w3.y;
        }
        if (t >= 3) {
            float4 a = x4[(size_t)(t - 3) * 1536 + c4];
            acc.x += a.x * w0.x; acc.y += a.y * w1.x;
            acc.z += a.z * w2.x; acc.w += a.w * w3.x;
        }
        acc.x = acc.x / (1.f + expf(-acc.x));
        acc.y = acc.y / (1.f + expf(-acc.y));
        acc.z = acc.z / (1.f + expf(-acc.z));
        acc.w = acc.w / (1.f + expf(-acc.w));
        sbuf4[c4] = acc;
    }
    __syncthreads();

    // l2-norm factors: groups 0..15 = q heads, 16..31 = k heads
    const int wid = tid >> 5, lane = tid & 31;
    for (int g = wid; g < 32; g += 8) {
        const int base = g * 128;
        float v0 = sbuf[base + lane];
        float v1 = sbuf[base + 32 + lane];
        float v2 = sbuf[base + 64 + lane];
        float v3 = sbuf[base + 96 + lane];
        float ss = v0 * v0 + v1 * v1 + v2 * v2 + v3 * v3;
        #pragma unroll
        for (int off = 16; off > 0; off >>= 1)
            ss += __shfl_xor_sync(0xffffffffu, ss, off);
        if (lane == 0) snorm[g] = rsqrtf(ss + 1e-6f);
    }
    __syncthreads();

    // write q, k, v into [H][T][D] (float4)
    const float qscale = 0.08838834764831845f;   // D^-0.5
    #pragma unroll
    for (int it = 0; it < 6; it++) {
        int c4 = tid + it * 256;
        int c  = c4 * 4;
        float4 val = sbuf4[c4];
        if (c < HD) {
            int h = c >> 7, d = c & 127;
            float sc = snorm[h] * qscale;
            val.x *= sc; val.y *= sc; val.z *= sc; val.w *= sc;
            ((float4*)g_q)[((size_t)h * TT + t) * 32 + (d >> 2)] = val;
        } else if (c < 2 * HD) {
            int cc = c - HD; int h = cc >> 7, d = cc & 127;
            float sc = snorm[16 + h];
            val.x *= sc; val.y *= sc; val.z *= sc; val.w *= sc;
            ((float4*)g_k)[((size_t)h * TT + t) * 32 + (d >> 2)] = val;
        } else {
            int cc = c - 2 * HD; int h = cc >> 7, d = cc & 127;
            ((float4*)g_v)[((size_t)h * TT + t) * 32 + (d >> 2)] = val;
        }
    }

    // decay gate (float4)
    const float4* fg4  = (const float4*)fg;      // [T, 512]
    const float4* dtb4 = (const float4*)dtb;     // [512]
    #pragma unroll
    for (int it = 0; it < 2; it++) {
        int c4 = tid + it * 256;                 // 0..511
        int h  = (c4 * 4) >> 7;
        float na = snegA[h];
        float4 gg = fg4[(size_t)t * 512 + c4];
        float4 bb = dtb4[c4];
        float4 r;
        r.x = expf(na * softplusf(gg.x + bb.x));
        r.y = expf(na * softplusf(gg.y + bb.y));
        r.z = expf(na * softplusf(gg.z + bb.z));
        r.w = expf(na * softplusf(gg.w + bb.w));
        ((float4*)g_dec)[((size_t)h * TT + t) * 32 + (((c4 * 4) & 127) >> 2)] = r;
    }
    if (tid < HH)
        g_b[tid * TT + t] = 1.f / (1.f + expf(-beta[(size_t)t * HH + tid]));
}

// ============================================================================
// Phase 2: pair-step delta-rule scan, cp.async smem pipeline.
// Grid (8,16), 128 threads. cl=tid>>3 (column), s=tid&7 (k-subrange of 16).
// ============================================================================

#define LOAD8(R, arr, buf, i) do {                                          \
    const ulonglong2* _p = &arr[buf][i][ss];                                \
    ulonglong2 _c0 = _p[0], _c1 = _p[8], _c2 = _p[16], _c3 = _p[24];        \
    R[0]=_c0.x; R[1]=_c0.y; R[2]=_c1.x; R[3]=_c1.y;                         \
    R[4]=_c2.x; R[5]=_c2.y; R[6]=_c3.x; R[7]=_c3.y;                         \
} while (0)

#define PREFETCH(buf, t0) do {                                              \
    _Pragma("unroll")                                                       \
    for (int _j = 0; _j < 2; _j++) {                                        \
        int _c = tid + _j * 128;                                            \
        int _st = _c >> 5, _cc = _c & 31;                                   \
        int _pos = ((_cc & 3) << 3) | (_cc >> 2);                           \
        size_t _go = (size_t)((t0) + _st) * DD + _cc * 4;                   \
        cpa16(&sk[buf][_st][_pos], kg + _go);                               \
        cpa16(&sd[buf][_st][_pos], dg + _go);                               \
        cpa16(&sq[buf][_st][_pos], qg + _go);                               \
    }                                                                       \
    if (tid < 32) {                                                         \
        int _st = tid >> 2, _part = tid & 3;                                \
        cpa16(&sv[buf][_st][_part * 4],                                     \
              vg + (size_t)((t0) + _st) * DD + _part * 4);                  \
    } else if (tid < 34) {                                                  \
        int _j = tid - 32;                                                  \
        cpa16(&sb[buf][_j * 4], bg + (t0) + _j * 4);                        \
    }                                                                       \
} while (0)

__global__ void __launch_bounds__(128, 1)
kda_scan_kernel(float* __restrict__ out)
{
    __shared__ __align__(16) ulonglong2 sk[2][GS][32];
    __shared__ __align__(16) ulonglong2 sd[2][GS][32];
    __shared__ __align__(16) ulonglong2 sq[2][GS][32];
    __shared__ __align__(16) float      sv[2][GS][16];
    __shared__ __align__(16) float      sb[2][GS];

    const int h   = blockIdx.y;
    const int cb  = blockIdx.x;
    const int tid = threadIdx.x;
    const int cl  = tid >> 3;            // 0..15 column within block
    const int s   = tid & 7;             // k-subrange 0..7
    const int ss  = s;
    const int col = cb * CPB + cl;

    const size_t hbase = (size_t)h * TT * DD;
    const float* kg = g_k   + hbase;
    const float* dg = g_dec + hbase;
    const float* qg = g_q   + hbase;
    const float* vg = g_v   + hbase + cb * CPB;
    const float* bg = g_b   + (size_t)h * TT;
    float* op = out + (size_t)h * DD + col;     // + t*H*D per step

    u64 st[8];
    #pragma unroll
    for (int i = 0; i < 8; i++) st[i] = 0ull;
    float o1pend = 0.f;                  // deferred o partial (prev pair's 2nd step)

    PREFETCH(0, 0);
    asm volatile("cp.async.commit_group;" ::: "memory");
    PREFETCH(1, GS);
    asm volatile("cp.async.commit_group;" ::: "memory");

    #pragma unroll 1
    for (int t0 = 0; t0 < TT; t0 += GS) {
        const int buf = (t0 >> 3) & 1;
        asm volatile("cp.async.wait_group 1;" ::: "memory");
        __syncthreads();

        #pragma unroll
        for (int i = 0; i < GS; i += 2) {
            const int tcur = t0 + i;
            float v0  = sv[buf][i][cl],     b0f = sb[buf][i];
            float v1  = sv[buf][i + 1][cl], b1f = sb[buf][i + 1];

            // ---- phase 0: P = D0∘S (frees st) ----
            u64 D0[8];  LOAD8(D0, sd, buf, i);
            u64 P[8];
            #pragma unroll
            for (int j = 0; j < 8; j++) P[j] = mul2(D0[j], st[j]);

            // ---- phase 1: partials using K0, Q0, P ----
            u64 K0[8];  LOAD8(K0, sk, buf, i);
            u64 Q0[8];  LOAD8(Q0, sq, buf, i);
            u64 akmt0 = 0, akmt1 = 0, acq0 = 0, acq1 = 0, ao0 = 0, ao1 = 0;
            #pragma unroll
            for (int j = 0; j < 8; j += 2) {
                akmt0 = fma2(K0[j], P[j], akmt0);  akmt1 = fma2(K0[j+1], P[j+1], akmt1);
                ao0   = fma2(Q0[j], P[j], ao0);    ao1   = fma2(Q0[j+1], P[j+1], ao1);
                acq0  = fma2(K0[j], Q0[j], acq0);  acq1  = fma2(K0[j+1], Q0[j+1], acq1);
            }

            // ---- phase 2: kp = D1∘K0, P2 = D1∘P (frees K0, P, D1) ----
            u64 D1[8];  LOAD8(D1, sd, buf, i + 1);
            u64 kp[8], P2[8];
            #pragma unroll
            for (int j = 0; j < 8; j++) {
                kp[j] = mul2(D1[j], K0[j]);
                P2[j] = mul2(D1[j], P[j]);
            }

            // ---- phase 3: kma = K1·P2, c = K1·kp ----
            u64 K1[8];  LOAD8(K1, sk, buf, i + 1);
            u64 akma0 = 0, akma1 = 0, ac0 = 0, ac1 = 0;
            #pragma unroll
            for (int j = 0; j < 8; j += 2) {
                akma0 = fma2(K1[j], P2[j], akma0); akma1 = fma2(K1[j+1], P2[j+1], akma1);
                ac0   = fma2(K1[j], kp[j], ac0);   ac1   = fma2(K1[j+1], kp[j+1], ac1);
            }

            // ---- phase 4: six concurrent shfl reductions ----
            float r0 = hsum2(add2(akmt0, akmt1));   // km_t
            float r1 = hsum2(add2(akma0, akma1));   // km_a
            float r2 = hsum2(add2(ac0, ac1));       // c
            float r3 = hsum2(add2(acq0, acq1));     // cq
            float r4 = hsum2(add2(ao0, ao1));       // o0 partial
            float r5 = o1pend;                      // deferred o1 from prev pair
            #pragma unroll
            for (int off = 1; off < 8; off <<= 1) {
                r0 += __shfl_xor_sync(0xffffffffu, r0, off);
                r1 += __shfl_xor_sync(0xffffffffu, r1, off);
                r2 += __shfl_xor_sync(0xffffffffu, r2, off);
                r3 += __shfl_xor_sync(0xffffffffu, r3, off);
                r4 += __shfl_xor_sync(0xffffffffu, r4, off);
                r5 += __shfl_xor_sync(0xffffffffu, r5, off);
            }

            // ---- phase 5: scalar recurrence + stores ----
            if (s == 0 && tcur > 0) op[(size_t)(tcur - 1) * HD] = r5;
            float d0 = b0f * (v0 - r0);
            if (s == 0) op[(size_t)tcur * HD] = fmaf(r3, d0, r4);
            float d1 = b1f * (v1 - r1 - r2 * d0);
            u64 dd0 = pack2(d0), dd1 = pack2(d1);

            // ---- phase 6: state update + deferred o1 partial ----
            u64 Q1[8];  LOAD8(Q1, sq, buf, i + 1);
            u64 aoo0 = 0, aoo1 = 0;
            #pragma unroll
            for (int j = 0; j < 8; j++) {
                u64 t1 = fma2(kp[j], dd0, P2[j]);
                st[j]  = fma2(K1[j], dd1, t1);
            }
            #pragma unroll
            for (int j = 0; j < 8; j += 2) {
                aoo0 = fma2(Q1[j], st[j], aoo0);
                aoo1 = fma2(Q1[j+1], st[j+1], aoo1);
            }
            o1pend = hsum2(add2(aoo0, aoo1));
        }

        __syncthreads();
        if (t0 + 2 * GS < TT) {
            PREFETCH(buf, t0 + 2 * GS);
        }
        asm volatile("cp.async.commit_group;" ::: "memory");
    }

    // tail: emit final deferred output (t = TT-1)
    float r = o1pend;
    #pragma unroll
    for (int off = 1; off < 8; off <<= 1)
        r += __shfl_xor_sync(0xffffffffu, r, off);
    if (s == 0) op[(size_t)(TT - 1) * HD] = r;
}

// ============================================================================
extern "C" void kernel_launch(void* const* d_in, const int* in_sizes, int n_in,
                              void* d_out, int out_size)
{
    const float* mixed = (const float*)d_in[0];   // [T, 3HD]
    const float* fg    = (const float*)d_in[1];   // [T, HD]
    const float* beta  = (const float*)d_in[2];   // [T, H]
    const float* cw    = (const float*)d_in[3];   // [3HD, 4]
    const float* dtb   = (const float*)d_in[4];   // [H, D]
    const float* alog  = (const float*)d_in[5];   // [H]
    float* out = (float*)d_out;                   // [T, H, D] f32

    prep_kernel<<<TT, 256>>>(mixed, fg, beta, cw, dtb, alog);
    kda_scan_kernel<<<dim3(NCB, HH), 128>>>(out);
}